// round 2
// baseline (speedup 1.0000x reference)
#include <cuda_runtime.h>
#include <math.h>

#define HD 128
#define NMAX 100000
#define EMAX 1600000

// ---------------- scratch (static device memory; no allocation) ----------------
__device__ float g_h[(size_t)NMAX * HD];     // LSTM output
__device__ float g_t[(size_t)NMAX * HD];     // transform output (row-scaled by dinv)
__device__ float g_s[(size_t)NMAX * HD];     // aggregation output
__device__ float g_dinv[NMAX];
__device__ int   g_deg[NMAX];                // edge-only in-degree
__device__ int   g_off[NMAX];                // CSR row starts
__device__ int   g_cur[NMAX];                // fill cursors
__device__ int   g_csr[EMAX];                // CSR src indices
__device__ int   g_bsums[256];               // scan partials
__device__ float g_wg[3 * HD * HD];          // LSTM weights, planes i,g,o, [k][j]
__device__ float g_gb[3 * HD];               // combined gate biases
__device__ float g_w3t[HD * HD];             // W3 transposed to [k][o]

// ---------------- prep: reshape weights ----------------
__global__ void prep_weights(const float* __restrict__ Wih,
                             const float* __restrict__ bih,
                             const float* __restrict__ bhh,
                             const float* __restrict__ W3) {
    int idx = blockIdx.x * blockDim.x + threadIdx.x;
    if (idx < 3 * HD * HD) {
        const int G[3] = {0, 256, 384};   // i, g, o row blocks in W_ih
        int p = idx / (HD * HD);
        int r = idx % (HD * HD);
        int k = r / HD, j = r % HD;
        g_wg[idx] = Wih[(G[p] + j) * HD + k];
    }
    if (idx < HD * HD) {
        int k = idx / HD, o = idx % HD;
        g_w3t[idx] = W3[o * HD + k];
    }
    if (idx < 3 * HD) {
        const int G[3] = {0, 256, 384};
        int p = idx / HD, j = idx % HD;
        g_gb[idx] = bih[G[p] + j] + bhh[G[p] + j];
    }
}

// ---------------- degree / dinv ----------------
__global__ void zero_deg(int n) {
    int i = blockIdx.x * blockDim.x + threadIdx.x;
    if (i < n) g_deg[i] = 0;
}

__global__ void deg_count(const int* __restrict__ ei, int e) {
    int i = blockIdx.x * blockDim.x + threadIdx.x;
    if (i < e) atomicAdd(&g_deg[ei[e + i]], 1);
}

__global__ void dinv_k(int n) {
    int i = blockIdx.x * blockDim.x + threadIdx.x;
    if (i < n) g_dinv[i] = rsqrtf((float)g_deg[i] + 1.0f);   // + self loop
}

// ---------------- exclusive scan of g_deg -> g_off ----------------
__global__ void scan1(int n) {
    __shared__ int sm[1024];
    int t = threadIdx.x;
    int i = blockIdx.x * 1024 + t;
    int v = (i < n) ? g_deg[i] : 0;
    sm[t] = v;
    __syncthreads();
    for (int o = 1; o < 1024; o <<= 1) {
        int tmp = (t >= o) ? sm[t - o] : 0;
        __syncthreads();
        sm[t] += tmp;
        __syncthreads();
    }
    if (i < n) g_off[i] = sm[t] - v;          // exclusive within block
    if (t == 1023) g_bsums[blockIdx.x] = sm[1023];
}

__global__ void scan2(int nb) {               // nb <= 128, single block of 128
    __shared__ int sm[128];
    int t = threadIdx.x;
    int v = (t < nb) ? g_bsums[t] : 0;
    sm[t] = v;
    __syncthreads();
    for (int o = 1; o < 128; o <<= 1) {
        int tmp = (t >= o) ? sm[t - o] : 0;
        __syncthreads();
        sm[t] += tmp;
        __syncthreads();
    }
    if (t < nb) g_bsums[t] = sm[t] - v;       // exclusive
}

__global__ void scan3(int n) {
    int i = blockIdx.x * blockDim.x + threadIdx.x;
    if (i < n) {
        int o = g_off[i] + g_bsums[i >> 10];
        g_off[i] = o;
        g_cur[i] = o;
    }
}

__global__ void csr_fill(const int* __restrict__ ei, int e) {
    int i = blockIdx.x * blockDim.x + threadIdx.x;
    if (i < e) {
        int d = ei[e + i];
        int pos = atomicAdd(&g_cur[d], 1);
        g_csr[pos] = ei[i];
    }
}

// ---------------- tiled fp32 GEMM: C[n x 128] = A[n x 128] @ B[128 x 128] ----------------
// MODE 0: LSTM (3 B-planes, activation epilogue, bias = gate biases)
// MODE 1: conv transform (epilogue: scale row by dinv)
// MODE 2: final (epilogue: relu(acc + bias[col]))
// ARELU:  apply relu to A elements on load
template <int MODE, bool ARELU>
__global__ void __launch_bounds__(256, 2)
gemm_k(const float* __restrict__ A,
       const float* __restrict__ B0, const float* __restrict__ B1,
       const float* __restrict__ B2,
       const float* __restrict__ bias, const float* __restrict__ dinv,
       float* __restrict__ C, int n) {
    constexpr int NP = (MODE == 0) ? 3 : 1;
    __shared__ float As[64 * 16];
    __shared__ float Bs[NP * 16 * 64];

    int tid = threadIdx.x;
    int tx = tid & 15, ty = tid >> 4;
    int r0 = blockIdx.x * 64;
    int c0 = blockIdx.y * 64;

    const float* Bp[3] = {B0, B1, B2};
    float acc[NP][16];
#pragma unroll
    for (int p = 0; p < NP; p++)
#pragma unroll
        for (int q = 0; q < 16; q++) acc[p][q] = 0.0f;

#pragma unroll 1
    for (int kt = 0; kt < 8; kt++) {
        // load A tile 64x16 (float4 per thread)
        {
            int row = tid >> 2, kq = tid & 3;
            int r = r0 + row;
            float4 av = make_float4(0.f, 0.f, 0.f, 0.f);
            if (r < n) av = *(const float4*)(A + (size_t)r * HD + kt * 16 + kq * 4);
            if (ARELU) {
                av.x = fmaxf(av.x, 0.f); av.y = fmaxf(av.y, 0.f);
                av.z = fmaxf(av.z, 0.f); av.w = fmaxf(av.w, 0.f);
            }
            *(float4*)(As + row * 16 + kq * 4) = av;
        }
        // load B tile(s) 16x64
        {
            int bk = tid >> 4;
            int j4 = (tid & 15) * 4;
#pragma unroll
            for (int p = 0; p < NP; p++) {
                float4 bv = *(const float4*)(Bp[p] + (kt * 16 + bk) * HD + c0 + j4);
                *(float4*)(Bs + p * 1024 + bk * 64 + j4) = bv;
            }
        }
        __syncthreads();
#pragma unroll
        for (int kk = 0; kk < 16; kk++) {
            float a[4];
#pragma unroll
            for (int i = 0; i < 4; i++) a[i] = As[(ty * 4 + i) * 16 + kk];
#pragma unroll
            for (int p = 0; p < NP; p++) {
                float4 b = *(const float4*)(Bs + p * 1024 + kk * 64 + tx * 4);
#pragma unroll
                for (int i = 0; i < 4; i++) {
                    acc[p][i * 4 + 0] += a[i] * b.x;
                    acc[p][i * 4 + 1] += a[i] * b.y;
                    acc[p][i * 4 + 2] += a[i] * b.z;
                    acc[p][i * 4 + 3] += a[i] * b.w;
                }
            }
        }
        __syncthreads();
    }

    // epilogue
#pragma unroll
    for (int i = 0; i < 4; i++) {
        int r = r0 + ty * 4 + i;
        if (r >= n) continue;
        float dv = 0.f;
        if (MODE == 1) dv = dinv[r];
#pragma unroll
        for (int j = 0; j < 4; j++) {
            int c = c0 + tx * 4 + j;
            float v;
            if (MODE == 0) {
                float gi = acc[0][i * 4 + j] + bias[0 * HD + c];
                float gg = acc[(NP > 1) ? 1 : 0][i * 4 + j] + bias[1 * HD + c];
                float go = acc[(NP > 2) ? 2 : 0][i * 4 + j] + bias[2 * HD + c];
                float si = 1.0f / (1.0f + __expf(-gi));
                float so = 1.0f / (1.0f + __expf(-go));
                float cc = si * tanhf(gg);
                v = so * tanhf(cc);
            } else if (MODE == 1) {
                v = acc[0][i * 4 + j] * dv;
            } else {
                v = fmaxf(acc[0][i * 4 + j] + bias[c], 0.0f);
            }
            C[(size_t)r * HD + c] = v;
        }
    }
}

// ---------------- CSR aggregation: s[n] = dinv[n]*(t2[n] + sum_e t2[src]) + b ----------------
__global__ void aggregate_k(const float* __restrict__ t2,
                            const float* __restrict__ bias,
                            float* __restrict__ out, int n) {
    int w = (blockIdx.x * blockDim.x + threadIdx.x) >> 5;
    int lane = threadIdx.x & 31;
    if (w >= n) return;
    const float4* T = (const float4*)t2;
    float4 acc = T[(size_t)w * 32 + lane];    // self-loop term
    int s0 = g_off[w];
    int cnt = g_deg[w];
    int i = 0;
    for (; i + 3 < cnt; i += 4) {
        int a = g_csr[s0 + i], b = g_csr[s0 + i + 1];
        int c = g_csr[s0 + i + 2], d = g_csr[s0 + i + 3];
        float4 v1 = T[(size_t)a * 32 + lane];
        float4 v2 = T[(size_t)b * 32 + lane];
        float4 v3 = T[(size_t)c * 32 + lane];
        float4 v4 = T[(size_t)d * 32 + lane];
        acc.x += v1.x + v2.x + v3.x + v4.x;
        acc.y += v1.y + v2.y + v3.y + v4.y;
        acc.z += v1.z + v2.z + v3.z + v4.z;
        acc.w += v1.w + v2.w + v3.w + v4.w;
    }
    for (; i < cnt; i++) {
        int s = g_csr[s0 + i];
        float4 v = T[(size_t)s * 32 + lane];
        acc.x += v.x; acc.y += v.y; acc.z += v.z; acc.w += v.w;
    }
    float dv = g_dinv[w];
    float4 b4 = ((const float4*)bias)[lane];
    float4 o;
    o.x = acc.x * dv + b4.x;
    o.y = acc.y * dv + b4.y;
    o.z = acc.z * dv + b4.z;
    o.w = acc.w * dv + b4.w;
    ((float4*)out)[(size_t)w * 32 + lane] = o;
}

// ---------------- launch ----------------
extern "C" void kernel_launch(void* const* d_in, const int* in_sizes, int n_in,
                              void* d_out, int out_size) {
    const float* z   = (const float*)d_in[0];
    const int*   ei  = (const int*)d_in[1];     // edge_index is int32 (JAX x64 off)
    const float* Wih = (const float*)d_in[2];
    // d_in[3] = W_hh (unused: h0 = 0)
    const float* bih = (const float*)d_in[4];
    const float* bhh = (const float*)d_in[5];
    const float* W1  = (const float*)d_in[6];
    const float* b1  = (const float*)d_in[7];
    const float* W2  = (const float*)d_in[8];
    const float* b2  = (const float*)d_in[9];
    const float* W3  = (const float*)d_in[10];
    const float* b3  = (const float*)d_in[11];

    int n = in_sizes[0] / HD;
    int e = in_sizes[1] / 2;
    float* out = (float*)d_out;

    float *p_h, *p_t, *p_s, *p_dinv, *p_wg, *p_gb, *p_w3t;
    cudaGetSymbolAddress((void**)&p_h, g_h);
    cudaGetSymbolAddress((void**)&p_t, g_t);
    cudaGetSymbolAddress((void**)&p_s, g_s);
    cudaGetSymbolAddress((void**)&p_dinv, g_dinv);
    cudaGetSymbolAddress((void**)&p_wg, g_wg);
    cudaGetSymbolAddress((void**)&p_gb, g_gb);
    cudaGetSymbolAddress((void**)&p_w3t, g_w3t);

    int nb = (n + 1023) / 1024;

    prep_weights<<<(3 * HD * HD + 255) / 256, 256>>>(Wih, bih, bhh, W3);
    zero_deg<<<(n + 255) / 256, 256>>>(n);
    deg_count<<<(e + 255) / 256, 256>>>(ei, e);
    dinv_k<<<(n + 255) / 256, 256>>>(n);
    scan1<<<nb, 1024>>>(n);
    scan2<<<1, 128>>>(nb);
    scan3<<<(n + 255) / 256, 256>>>(n);
    csr_fill<<<(e + 255) / 256, 256>>>(ei, e);

    dim3 gg((n + 63) / 64, 2);
    // LSTM: h = act(z @ Wg + gb)
    gemm_k<0, false><<<gg, 256>>>(z, p_wg, p_wg + HD * HD, p_wg + 2 * HD * HD,
                                  p_gb, nullptr, p_h, n);
    // conv1 transform: t = (h @ W1) * dinv[row]
    gemm_k<1, false><<<gg, 256>>>(p_h, W1, nullptr, nullptr, nullptr, p_dinv, p_t, n);
    // conv1 aggregate: s = dinv*(t_self + sum t[src]) + b1
    aggregate_k<<<((size_t)n * 32 + 255) / 256, 256>>>(p_t, b1, p_s, n);
    // conv2 transform: t = (relu(s) @ W2) * dinv[row]
    gemm_k<1, true><<<gg, 256>>>(p_s, W2, nullptr, nullptr, nullptr, p_dinv, p_t, n);
    // conv2 aggregate: s = dinv*(t_self + sum t[src]) + b2
    aggregate_k<<<((size_t)n * 32 + 255) / 256, 256>>>(p_t, b2, p_s, n);
    // final: out = relu(s @ W3^T + b3)
    gemm_k<2, false><<<gg, 256>>>(p_s, p_w3t, nullptr, nullptr, b3, nullptr, out, n);
}

// round 4
// speedup vs baseline: 1.1150x; 1.1150x over previous
#include <cuda_runtime.h>
#include <cuda_bf16.h>
#include <math.h>
#include <stdint.h>

#define HD 128
#define NMAX 100000
#define EMAX 1600000

// ================= scratch (static device memory) =================
__device__ float g_h[(size_t)NMAX * HD];
__device__ float g_t[(size_t)NMAX * HD];
__device__ float g_s[(size_t)NMAX * HD];
__device__ float g_dinv[NMAX];
__device__ int   g_deg[NMAX];
__device__ int   g_off[NMAX];
__device__ int   g_cur[NMAX];
__device__ int   g_csr[EMAX];
__device__ int   g_bsums[256];
__device__ float g_gb[3 * HD];                       // combined gate biases (i,g,o)
__device__ __align__(16) __nv_bfloat16 g_wb[6 * 2 * HD * HD];  // [plane][hi/lo][128*128]
// planes: 0,1,2 = W_ih gate blocks (i,g,o) as [n][k]; 3 = W1^T; 4 = W2^T; 5 = W3

__device__ __forceinline__ void split_bf16(float v, __nv_bfloat16& h, __nv_bfloat16& l) {
    h = __float2bfloat16(v);
    l = __float2bfloat16(v - __bfloat162float(h));
}

// ================= prep: split weights to bf16 hi/lo planes =================
__global__ void prep_weights(const float* __restrict__ Wih,
                             const float* __restrict__ W1,
                             const float* __restrict__ W2,
                             const float* __restrict__ W3,
                             const float* __restrict__ bih,
                             const float* __restrict__ bhh) {
    int idx = blockIdx.x * blockDim.x + threadIdx.x;
    if (idx >= HD * HD) return;
    int nn = idx >> 7, kk = idx & 127;
    const int G[3] = {0, 256, 384};   // i, g, o gate row blocks
    float src[6];
    src[0] = Wih[(G[0] + nn) * HD + kk];
    src[1] = Wih[(G[1] + nn) * HD + kk];
    src[2] = Wih[(G[2] + nn) * HD + kk];
    src[3] = W1[kk * HD + nn];        // W1^T: Bs[n][k] = W1[k][n]
    src[4] = W2[kk * HD + nn];
    src[5] = W3[nn * HD + kk];        // W3 natural: Bs[n][k] = W3[n][k]
#pragma unroll
    for (int p = 0; p < 6; p++) {
        __nv_bfloat16 h, l;
        split_bf16(src[p], h, l);
        g_wb[p * 32768 + idx] = h;
        g_wb[p * 32768 + 16384 + idx] = l;
    }
    if (idx < 3 * HD) {
        int p = idx / HD, j = idx % HD;
        g_gb[idx] = bih[G[p] + j] + bhh[G[p] + j];
    }
}

// ================= degree / scan / CSR =================
__global__ void zero_deg(int n) {
    int i = blockIdx.x * blockDim.x + threadIdx.x;
    if (i < n) g_deg[i] = 0;
}
__global__ void deg_count(const int* __restrict__ ei, int e) {
    int i = blockIdx.x * blockDim.x + threadIdx.x;
    if (i < e) atomicAdd(&g_deg[ei[e + i]], 1);
}
__global__ void dinv_k(int n) {
    int i = blockIdx.x * blockDim.x + threadIdx.x;
    if (i < n) g_dinv[i] = rsqrtf((float)g_deg[i] + 1.0f);
}
__global__ void scan1(int n) {
    __shared__ int sm[1024];
    int t = threadIdx.x, i = blockIdx.x * 1024 + t;
    int v = (i < n) ? g_deg[i] : 0;
    sm[t] = v; __syncthreads();
    for (int o = 1; o < 1024; o <<= 1) {
        int tmp = (t >= o) ? sm[t - o] : 0; __syncthreads();
        sm[t] += tmp; __syncthreads();
    }
    if (i < n) g_off[i] = sm[t] - v;
    if (t == 1023) g_bsums[blockIdx.x] = sm[1023];
}
__global__ void scan2(int nb) {
    __shared__ int sm[128];
    int t = threadIdx.x;
    int v = (t < nb) ? g_bsums[t] : 0;
    sm[t] = v; __syncthreads();
    for (int o = 1; o < 128; o <<= 1) {
        int tmp = (t >= o) ? sm[t - o] : 0; __syncthreads();
        sm[t] += tmp; __syncthreads();
    }
    if (t < nb) g_bsums[t] = sm[t] - v;
}
__global__ void scan3(int n) {
    int i = blockIdx.x * blockDim.x + threadIdx.x;
    if (i < n) {
        int o = g_off[i] + g_bsums[i >> 10];
        g_off[i] = o; g_cur[i] = o;
    }
}
__global__ void csr_fill(const int* __restrict__ ei, int e) {
    int i = blockIdx.x * blockDim.x + threadIdx.x;
    if (i < e) {
        int d = ei[e + i];
        g_csr[atomicAdd(&g_cur[d], 1)] = ei[i];
    }
}

// ================= mma.sync bf16 split GEMM =================
// C[n x 128] = epi(A[n x 128] @ B)   B given as bf16 hi/lo planes [n][k]
// MODE 0: raw store, 1: row scale by dinv, 2: relu(acc + bias[col])
// NY: number of B planes spread over blockIdx.y (3 for LSTM gates)
__device__ __forceinline__ void mma_bf16(float* d, const uint32_t* a, const uint32_t* b) {
    asm volatile(
        "mma.sync.aligned.m16n8k16.row.col.f32.bf16.bf16.f32 "
        "{%0,%1,%2,%3}, {%4,%5,%6,%7}, {%8,%9}, {%0,%1,%2,%3};"
        : "+f"(d[0]), "+f"(d[1]), "+f"(d[2]), "+f"(d[3])
        : "r"(a[0]), "r"(a[1]), "r"(a[2]), "r"(a[3]), "r"(b[0]), "r"(b[1]));
}

#define SMS 144   // SMEM row stride in bytes (72 bf16): conflict-free fragment LDS

template <int MODE, bool ARELU, int NY>
__global__ void __launch_bounds__(256, 2)
mma_gemm(const float* __restrict__ A, const __nv_bfloat16* __restrict__ Bplanes,
         const float* __restrict__ bias, const float* __restrict__ dinv,
         float* __restrict__ C0, float* __restrict__ C1, float* __restrict__ C2,
         int n) {
    extern __shared__ char sm[];
    const int AHI = 0, ALO = 18432, BHI = 36864, BLO = 55296;

    int tid = threadIdx.x, lane = tid & 31, wid = tid >> 5;
    int gid = lane >> 2, tig = lane & 3;
    int wm = wid & 3, wn = wid >> 2;
    int r0 = blockIdx.x * 128;

    const __nv_bfloat16* Bp = Bplanes + (size_t)blockIdx.y * 32768;
    float* C = C0;
    if (NY == 3) C = (blockIdx.y == 0) ? C0 : ((blockIdx.y == 1) ? C1 : C2);

    float acc[2][8][4];
#pragma unroll
    for (int mt = 0; mt < 2; mt++)
#pragma unroll
        for (int nt = 0; nt < 8; nt++)
#pragma unroll
            for (int q = 0; q < 4; q++) acc[mt][nt][q] = 0.0f;

#pragma unroll 1
    for (int kc = 0; kc < 2; kc++) {
        // ---- load + split A chunk (128 rows x 64 k) ----
        for (int i = tid; i < 128 * 16; i += 256) {
            int row = i >> 4, q = i & 15;
            float4 v = make_float4(0.f, 0.f, 0.f, 0.f);
            if (r0 + row < n)
                v = *(const float4*)(A + (size_t)(r0 + row) * HD + kc * 64 + q * 4);
            if (ARELU) {
                v.x = fmaxf(v.x, 0.f); v.y = fmaxf(v.y, 0.f);
                v.z = fmaxf(v.z, 0.f); v.w = fmaxf(v.w, 0.f);
            }
            __nv_bfloat16 h[4], l[4];
            split_bf16(v.x, h[0], l[0]); split_bf16(v.y, h[1], l[1]);
            split_bf16(v.z, h[2], l[2]); split_bf16(v.w, h[3], l[3]);
            *(uint2*)(sm + AHI + row * SMS + q * 8) = *(const uint2*)h;
            *(uint2*)(sm + ALO + row * SMS + q * 8) = *(const uint2*)l;
        }
        // ---- load B chunk (bf16, pre-split) ----
        for (int i = tid; i < 128 * 8; i += 256) {
            int row = i >> 3, q = i & 7;
            uint4 h = *(const uint4*)(Bp + (size_t)row * HD + kc * 64 + q * 8);
            uint4 l = *(const uint4*)(Bp + 16384 + (size_t)row * HD + kc * 64 + q * 8);
            *(uint4*)(sm + BHI + row * SMS + q * 16) = h;
            *(uint4*)(sm + BLO + row * SMS + q * 16) = l;
        }
        __syncthreads();

#pragma unroll
        for (int s = 0; s < 3; s++) {
            int Ab = (s == 1) ? ALO : AHI;
            int Bb = (s == 2) ? BLO : BHI;
#pragma unroll
            for (int ks = 0; ks < 4; ks++) {
                uint32_t ra[2][4];
#pragma unroll
                for (int mt = 0; mt < 2; mt++) {
                    int r = wm * 32 + mt * 16 + gid;
                    const char* p = sm + Ab + r * SMS + (ks * 16 + tig * 2) * 2;
                    ra[mt][0] = *(const uint32_t*)p;
                    ra[mt][1] = *(const uint32_t*)(p + 8 * SMS);
                    ra[mt][2] = *(const uint32_t*)(p + 16);
                    ra[mt][3] = *(const uint32_t*)(p + 8 * SMS + 16);
                }
#pragma unroll
                for (int nt = 0; nt < 8; nt++) {
                    int nr = wn * 64 + nt * 8 + gid;
                    const char* p = sm + Bb + nr * SMS + (ks * 16 + tig * 2) * 2;
                    uint32_t rb[2];
                    rb[0] = *(const uint32_t*)p;
                    rb[1] = *(const uint32_t*)(p + 16);
                    mma_bf16(acc[0][nt], ra[0], rb);
                    mma_bf16(acc[1][nt], ra[1], rb);
                }
            }
        }
        __syncthreads();
    }

    // ---- epilogue: direct STG (float2 per row-fragment) ----
#pragma unroll
    for (int mt = 0; mt < 2; mt++) {
        int row0 = r0 + wm * 32 + mt * 16 + gid;
        int row1 = row0 + 8;
        float dv0 = 0.f, dv1 = 0.f;
        if (MODE == 1) {
            dv0 = (row0 < n) ? dinv[row0] : 0.f;
            dv1 = (row1 < n) ? dinv[row1] : 0.f;
        }
#pragma unroll
        for (int nt = 0; nt < 8; nt++) {
            int col = wn * 64 + nt * 8 + tig * 2;
            float d0 = acc[mt][nt][0], d1 = acc[mt][nt][1];
            float d2 = acc[mt][nt][2], d3 = acc[mt][nt][3];
            if (MODE == 1) { d0 *= dv0; d1 *= dv0; d2 *= dv1; d3 *= dv1; }
            if (MODE == 2) {
                float b0 = __ldg(bias + col), b1 = __ldg(bias + col + 1);
                d0 = fmaxf(d0 + b0, 0.f); d1 = fmaxf(d1 + b1, 0.f);
                d2 = fmaxf(d2 + b0, 0.f); d3 = fmaxf(d3 + b1, 0.f);
            }
            if (row0 < n) *(float2*)(C + (size_t)row0 * HD + col) = make_float2(d0, d1);
            if (row1 < n) *(float2*)(C + (size_t)row1 * HD + col) = make_float2(d2, d3);
        }
    }
}

// ================= LSTM activation (elementwise over raw gates) =================
// g_h = i-gate raw, g_t = g-gate raw, g_s = o-gate raw; result -> g_h
__global__ void lstm_act(int n) {
    int i4 = blockIdx.x * blockDim.x + threadIdx.x;
    if (i4 >= n * 32) return;
    int row = i4 >> 5, q = i4 & 31;
    size_t off = (size_t)row * HD + q * 4;
    float4 vi = *(const float4*)(g_h + off);
    float4 vg = *(const float4*)(g_t + off);
    float4 vo = *(const float4*)(g_s + off);
    float4 bi = *(const float4*)(g_gb + q * 4);
    float4 bg = *(const float4*)(g_gb + 128 + q * 4);
    float4 bo = *(const float4*)(g_gb + 256 + q * 4);
    float4 r;
#define ACT(c) { \
        float si = 1.0f / (1.0f + __expf(-(vi.c + bi.c))); \
        float so = 1.0f / (1.0f + __expf(-(vo.c + bo.c))); \
        float cc = si * tanhf(vg.c + bg.c); \
        r.c = so * tanhf(cc); }
    ACT(x) ACT(y) ACT(z) ACT(w)
#undef ACT
    *(float4*)(g_h + off) = r;
}

// ================= CSR aggregation =================
__global__ void aggregate_k(const float* __restrict__ t2,
                            const float* __restrict__ bias,
                            float* __restrict__ out, int n) {
    int w = (blockIdx.x * blockDim.x + threadIdx.x) >> 5;
    int lane = threadIdx.x & 31;
    if (w >= n) return;
    const float4* T = (const float4*)t2;
    float4 acc = T[(size_t)w * 32 + lane];
    int s0 = g_off[w], cnt = g_deg[w];
    int i = 0;
    for (; i + 3 < cnt; i += 4) {
        int a = g_csr[s0 + i], b = g_csr[s0 + i + 1];
        int c = g_csr[s0 + i + 2], d = g_csr[s0 + i + 3];
        float4 v1 = T[(size_t)a * 32 + lane];
        float4 v2 = T[(size_t)b * 32 + lane];
        float4 v3 = T[(size_t)c * 32 + lane];
        float4 v4 = T[(size_t)d * 32 + lane];
        acc.x += v1.x + v2.x + v3.x + v4.x;
        acc.y += v1.y + v2.y + v3.y + v4.y;
        acc.z += v1.z + v2.z + v3.z + v4.z;
        acc.w += v1.w + v2.w + v3.w + v4.w;
    }
    for (; i < cnt; i++) {
        float4 v = T[(size_t)g_csr[s0 + i] * 32 + lane];
        acc.x += v.x; acc.y += v.y; acc.z += v.z; acc.w += v.w;
    }
    float dvv = g_dinv[w];
    float4 b4 = ((const float4*)bias)[lane];
    float4 o;
    o.x = acc.x * dvv + b4.x; o.y = acc.y * dvv + b4.y;
    o.z = acc.z * dvv + b4.z; o.w = acc.w * dvv + b4.w;
    ((float4*)out)[(size_t)w * 32 + lane] = o;
}

// ================= launch =================
#define SMEM_GEMM 73728

extern "C" void kernel_launch(void* const* d_in, const int* in_sizes, int n_in,
                              void* d_out, int out_size) {
    const float* z   = (const float*)d_in[0];
    const int*   ei  = (const int*)d_in[1];
    const float* Wih = (const float*)d_in[2];
    const float* bih = (const float*)d_in[4];
    const float* bhh = (const float*)d_in[5];
    const float* W1  = (const float*)d_in[6];
    const float* b1  = (const float*)d_in[7];
    const float* W2  = (const float*)d_in[8];
    const float* b2  = (const float*)d_in[9];
    const float* W3  = (const float*)d_in[10];
    const float* b3  = (const float*)d_in[11];

    int n = in_sizes[0] / HD;
    int e = in_sizes[1] / 2;
    float* out = (float*)d_out;

    float *p_h, *p_t, *p_s, *p_dinv;
    __nv_bfloat16* p_wb;
    cudaGetSymbolAddress((void**)&p_h, g_h);
    cudaGetSymbolAddress((void**)&p_t, g_t);
    cudaGetSymbolAddress((void**)&p_s, g_s);
    cudaGetSymbolAddress((void**)&p_dinv, g_dinv);
    cudaGetSymbolAddress((void**)&p_wb, g_wb);

    cudaFuncSetAttribute(mma_gemm<0, false, 3>, cudaFuncAttributeMaxDynamicSharedMemorySize, SMEM_GEMM);
    cudaFuncSetAttribute(mma_gemm<1, false, 1>, cudaFuncAttributeMaxDynamicSharedMemorySize, SMEM_GEMM);
    cudaFuncSetAttribute(mma_gemm<1, true, 1>,  cudaFuncAttributeMaxDynamicSharedMemorySize, SMEM_GEMM);
    cudaFuncSetAttribute(mma_gemm<2, false, 1>, cudaFuncAttributeMaxDynamicSharedMemorySize, SMEM_GEMM);

    int nb = (n + 1023) / 1024;
    prep_weights<<<(HD * HD + 255) / 256, 256>>>(Wih, W1, W2, W3, bih, bhh);
    zero_deg<<<(n + 255) / 256, 256>>>(n);
    deg_count<<<(e + 255) / 256, 256>>>(ei, e);
    dinv_k<<<(n + 255) / 256, 256>>>(n);
    scan1<<<nb, 1024>>>(n);
    scan2<<<1, 128>>>(nb);
    scan3<<<(n + 255) / 256, 256>>>(n);
    csr_fill<<<(e + 255) / 256, 256>>>(ei, e);

    dim3 gl((n + 127) / 128, 3);
    dim3 gg((n + 127) / 128, 1);
    // LSTM raw gates: i -> g_h, g -> g_t, o -> g_s
    mma_gemm<0, false, 3><<<gl, 256, SMEM_GEMM>>>(z, p_wb, nullptr, nullptr,
                                                  p_h, p_t, p_s, n);
    lstm_act<<<((size_t)n * 32 + 255) / 256, 256>>>(n);
    // conv1 transform: t = (h @ W1) * dinv[row]
    mma_gemm<1, false, 1><<<gg, 256, SMEM_GEMM>>>(p_h, p_wb + 3 * 32768, nullptr, p_dinv,
                                                  p_t, nullptr, nullptr, n);
    aggregate_k<<<((size_t)n * 32 + 255) / 256, 256>>>(p_t, b1, p_s, n);
    // conv2 transform: t = (relu(s) @ W2) * dinv[row]
    mma_gemm<1, true, 1><<<gg, 256, SMEM_GEMM>>>(p_s, p_wb + 4 * 32768, nullptr, p_dinv,
                                                 p_t, nullptr, nullptr, n);
    aggregate_k<<<((size_t)n * 32 + 255) / 256, 256>>>(p_t, b2, p_s, n);
    // final: out = relu(s @ W3^T + b3)
    mma_gemm<2, false, 1><<<gg, 256, SMEM_GEMM>>>(p_s, p_wb + 5 * 32768, b3, nullptr,
                                                  out, nullptr, nullptr, n);
}

// round 5
// speedup vs baseline: 1.4530x; 1.3031x over previous
#include <cuda_runtime.h>
#include <cuda_bf16.h>
#include <math.h>
#include <stdint.h>

#define HD 128
#define NMAX 100000
#define EMAX 1600000

// ================= scratch (static device memory) =================
__device__ float g_h[(size_t)NMAX * HD];
__device__ float g_t[(size_t)NMAX * HD];
__device__ float g_s[(size_t)NMAX * HD];
__device__ float g_dinv[NMAX];
__device__ int   g_deg[NMAX];
__device__ int   g_off[NMAX];
__device__ int   g_cur[NMAX];
__device__ int   g_csr[EMAX];
__device__ int   g_bsums[256];
__device__ float g_gb[3 * HD];                       // combined gate biases (i,g,o)
__device__ __align__(16) __nv_bfloat16 g_wb[6 * 2 * HD * HD];  // [plane][hi/lo][128*128]
// planes: 0,1,2 = W_ih gate blocks (i,g,o) as [n][k]; 3 = W1^T; 4 = W2^T; 5 = W3

__device__ __forceinline__ void split_bf16(float v, __nv_bfloat16& h, __nv_bfloat16& l) {
    h = __float2bfloat16(v);
    l = __float2bfloat16(v - __bfloat162float(h));
}

// ================= prep =================
__global__ void prep_weights(const float* __restrict__ Wih,
                             const float* __restrict__ W1,
                             const float* __restrict__ W2,
                             const float* __restrict__ W3,
                             const float* __restrict__ bih,
                             const float* __restrict__ bhh) {
    int idx = blockIdx.x * blockDim.x + threadIdx.x;
    if (idx >= HD * HD) return;
    int nn = idx >> 7, kk = idx & 127;
    const int G[3] = {0, 256, 384};
    float src[6];
    src[0] = Wih[(G[0] + nn) * HD + kk];
    src[1] = Wih[(G[1] + nn) * HD + kk];
    src[2] = Wih[(G[2] + nn) * HD + kk];
    src[3] = W1[kk * HD + nn];
    src[4] = W2[kk * HD + nn];
    src[5] = W3[nn * HD + kk];
#pragma unroll
    for (int p = 0; p < 6; p++) {
        __nv_bfloat16 h, l;
        split_bf16(src[p], h, l);
        g_wb[p * 32768 + idx] = h;
        g_wb[p * 32768 + 16384 + idx] = l;
    }
    if (idx < 3 * HD) {
        int p = idx / HD, j = idx % HD;
        g_gb[idx] = bih[G[p] + j] + bhh[G[p] + j];
    }
}

// ================= degree / scan / CSR =================
__global__ void zero_deg(int n) {
    int i = blockIdx.x * blockDim.x + threadIdx.x;
    if (i < n) g_deg[i] = 0;
}
__global__ void deg_count(const int* __restrict__ ei, int e) {
    int i = blockIdx.x * blockDim.x + threadIdx.x;
    if (i < e) atomicAdd(&g_deg[ei[e + i]], 1);
}
__global__ void scan1(int n) {
    __shared__ int sm[1024];
    int t = threadIdx.x, i = blockIdx.x * 1024 + t;
    int v = (i < n) ? g_deg[i] : 0;
    if (i < n) g_dinv[i] = rsqrtf((float)v + 1.0f);   // fused dinv
    sm[t] = v; __syncthreads();
    for (int o = 1; o < 1024; o <<= 1) {
        int tmp = (t >= o) ? sm[t - o] : 0; __syncthreads();
        sm[t] += tmp; __syncthreads();
    }
    if (i < n) g_off[i] = sm[t] - v;
    if (t == 1023) g_bsums[blockIdx.x] = sm[1023];
}
__global__ void scan2(int nb) {
    __shared__ int sm[128];
    int t = threadIdx.x;
    int v = (t < nb) ? g_bsums[t] : 0;
    sm[t] = v; __syncthreads();
    for (int o = 1; o < 128; o <<= 1) {
        int tmp = (t >= o) ? sm[t - o] : 0; __syncthreads();
        sm[t] += tmp; __syncthreads();
    }
    if (t < nb) g_bsums[t] = sm[t] - v;
}
__global__ void scan3(int n) {
    int i = blockIdx.x * blockDim.x + threadIdx.x;
    if (i < n) {
        int o = g_off[i] + g_bsums[i >> 10];
        g_off[i] = o; g_cur[i] = o;
    }
}
__global__ void csr_fill(const int* __restrict__ ei, int e) {
    int i = blockIdx.x * blockDim.x + threadIdx.x;
    if (i < e) {
        int d = ei[e + i];
        g_csr[atomicAdd(&g_cur[d], 1)] = ei[i];
    }
}

// ================= mma helpers =================
__device__ __forceinline__ void mma_bf16(float* d, const uint32_t* a, const uint32_t* b) {
    asm volatile(
        "mma.sync.aligned.m16n8k16.row.col.f32.bf16.bf16.f32 "
        "{%0,%1,%2,%3}, {%4,%5,%6,%7}, {%8,%9}, {%0,%1,%2,%3};"
        : "+f"(d[0]), "+f"(d[1]), "+f"(d[2]), "+f"(d[3])
        : "r"(a[0]), "r"(a[1]), "r"(a[2]), "r"(a[3]), "r"(b[0]), "r"(b[1]));
}

// ================= fused LSTM: h = act(z @ {Wi,Wg,Wo}^T + gb) =================
// 64-row tile, full K=128 resident. Planes sequential, acc reused, c in regs.
#define SMS2 272   // SMEM row stride bytes (68 words): conflict-free frag LDS
#define L_AHI 0
#define L_ALO 17408
#define L_BHI 34816
#define L_BLO 69632
#define L_TOT 104448

__global__ void __launch_bounds__(256, 2)
lstm_fused(const float* __restrict__ z, int n) {
    extern __shared__ char sm[];
    int tid = threadIdx.x, lane = tid & 31, wid = tid >> 5;
    int gid = lane >> 2, tig = lane & 3;
    int wm = wid >> 2, wn = wid & 3;            // 2 m x 4 n warps
    int r0 = blockIdx.x * 64;

    // ---- load + split A (64 x 128) ----
    for (int i = tid; i < 64 * 32; i += 256) {
        int row = i >> 5, q = i & 31;
        float4 v = make_float4(0.f, 0.f, 0.f, 0.f);
        if (r0 + row < n) v = *(const float4*)(z + (size_t)(r0 + row) * HD + q * 4);
        __nv_bfloat16 h[4], l[4];
        split_bf16(v.x, h[0], l[0]); split_bf16(v.y, h[1], l[1]);
        split_bf16(v.z, h[2], l[2]); split_bf16(v.w, h[3], l[3]);
        *(uint2*)(sm + L_AHI + row * SMS2 + q * 8) = *(const uint2*)h;
        *(uint2*)(sm + L_ALO + row * SMS2 + q * 8) = *(const uint2*)l;
    }

    float cp[2][4][4];   // running c (then used for h)
    float acc[2][4][4];

#pragma unroll 1
    for (int p = 0; p < 3; p++) {
        __syncthreads();   // prev-plane frag reads done before B overwrite
        // ---- load B plane p (128 x 128 bf16 hi/lo) ----
        for (int i = tid; i < 128 * 16; i += 256) {
            int row = i >> 4, q = i & 15;
            uint4 h = *(const uint4*)(g_wb + (size_t)p * 32768 + row * HD + q * 8);
            uint4 l = *(const uint4*)(g_wb + (size_t)p * 32768 + 16384 + row * HD + q * 8);
            *(uint4*)(sm + L_BHI + row * SMS2 + q * 16) = h;
            *(uint4*)(sm + L_BLO + row * SMS2 + q * 16) = l;
        }
        __syncthreads();

#pragma unroll
        for (int mt = 0; mt < 2; mt++)
#pragma unroll
            for (int nt = 0; nt < 4; nt++)
#pragma unroll
                for (int q = 0; q < 4; q++) acc[mt][nt][q] = 0.0f;

#pragma unroll
        for (int s = 0; s < 3; s++) {
            int Ab = (s == 1) ? L_ALO : L_AHI;
            int Bb = (s == 2) ? L_BLO : L_BHI;
#pragma unroll
            for (int ks = 0; ks < 8; ks++) {
                uint32_t ra[2][4];
#pragma unroll
                for (int mt = 0; mt < 2; mt++) {
                    int r = wm * 32 + mt * 16 + gid;
                    const char* pp = sm + Ab + r * SMS2 + (ks * 16 + tig * 2) * 2;
                    ra[mt][0] = *(const uint32_t*)pp;
                    ra[mt][1] = *(const uint32_t*)(pp + 8 * SMS2);
                    ra[mt][2] = *(const uint32_t*)(pp + 16);
                    ra[mt][3] = *(const uint32_t*)(pp + 8 * SMS2 + 16);
                }
#pragma unroll
                for (int nt = 0; nt < 4; nt++) {
                    int nr = wn * 32 + nt * 8 + gid;
                    const char* pp = sm + Bb + nr * SMS2 + (ks * 16 + tig * 2) * 2;
                    uint32_t rb[2];
                    rb[0] = *(const uint32_t*)pp;
                    rb[1] = *(const uint32_t*)(pp + 16);
                    mma_bf16(acc[0][nt], ra[0], rb);
                    mma_bf16(acc[1][nt], ra[1], rb);
                }
            }
        }

        // ---- plane epilogue ----
#pragma unroll
        for (int mt = 0; mt < 2; mt++) {
#pragma unroll
            for (int nt = 0; nt < 4; nt++) {
                int col = wn * 32 + nt * 8 + tig * 2;
                float2 bg = *(const float2*)(g_gb + p * HD + col);
#pragma unroll
                for (int q = 0; q < 4; q++) {
                    float gv = acc[mt][nt][q] + ((q & 1) ? bg.y : bg.x);
                    if (p == 0)      cp[mt][nt][q] = 1.0f / (1.0f + __expf(-gv));
                    else if (p == 1) cp[mt][nt][q] = cp[mt][nt][q] * tanhf(gv);
                    else             cp[mt][nt][q] = (1.0f / (1.0f + __expf(-gv))) * tanhf(cp[mt][nt][q]);
                }
            }
        }
    }

    // ---- store h ----
#pragma unroll
    for (int mt = 0; mt < 2; mt++) {
        int row0 = r0 + wm * 32 + mt * 16 + gid;
        int row1 = row0 + 8;
#pragma unroll
        for (int nt = 0; nt < 4; nt++) {
            int col = wn * 32 + nt * 8 + tig * 2;
            if (row0 < n) *(float2*)(g_h + (size_t)row0 * HD + col) = make_float2(cp[mt][nt][0], cp[mt][nt][1]);
            if (row1 < n) *(float2*)(g_h + (size_t)row1 * HD + col) = make_float2(cp[mt][nt][2], cp[mt][nt][3]);
        }
    }
}

// ================= mma.sync split GEMM (single plane) =================
// MODE 1: row scale by dinv; MODE 2: relu(acc + bias[col]); ARELU: relu A on load
#define SMS 144
template <int MODE, bool ARELU>
__global__ void __launch_bounds__(256, 2)
mma_gemm(const float* __restrict__ A, const __nv_bfloat16* __restrict__ Bp,
         const float* __restrict__ bias, const float* __restrict__ dinv,
         float* __restrict__ C, int n) {
    extern __shared__ char sm[];
    const int AHI = 0, ALO = 18432, BHI = 36864, BLO = 55296;

    int tid = threadIdx.x, lane = tid & 31, wid = tid >> 5;
    int gid = lane >> 2, tig = lane & 3;
    int wm = wid & 3, wn = wid >> 2;
    int r0 = blockIdx.x * 128;

    float acc[2][8][4];
#pragma unroll
    for (int mt = 0; mt < 2; mt++)
#pragma unroll
        for (int nt = 0; nt < 8; nt++)
#pragma unroll
            for (int q = 0; q < 4; q++) acc[mt][nt][q] = 0.0f;

#pragma unroll 1
    for (int kc = 0; kc < 2; kc++) {
        for (int i = tid; i < 128 * 16; i += 256) {
            int row = i >> 4, q = i & 15;
            float4 v = make_float4(0.f, 0.f, 0.f, 0.f);
            if (r0 + row < n)
                v = *(const float4*)(A + (size_t)(r0 + row) * HD + kc * 64 + q * 4);
            if (ARELU) {
                v.x = fmaxf(v.x, 0.f); v.y = fmaxf(v.y, 0.f);
                v.z = fmaxf(v.z, 0.f); v.w = fmaxf(v.w, 0.f);
            }
            __nv_bfloat16 h[4], l[4];
            split_bf16(v.x, h[0], l[0]); split_bf16(v.y, h[1], l[1]);
            split_bf16(v.z, h[2], l[2]); split_bf16(v.w, h[3], l[3]);
            *(uint2*)(sm + AHI + row * SMS + q * 8) = *(const uint2*)h;
            *(uint2*)(sm + ALO + row * SMS + q * 8) = *(const uint2*)l;
        }
        for (int i = tid; i < 128 * 8; i += 256) {
            int row = i >> 3, q = i & 7;
            uint4 h = *(const uint4*)(Bp + (size_t)row * HD + kc * 64 + q * 8);
            uint4 l = *(const uint4*)(Bp + 16384 + (size_t)row * HD + kc * 64 + q * 8);
            *(uint4*)(sm + BHI + row * SMS + q * 16) = h;
            *(uint4*)(sm + BLO + row * SMS + q * 16) = l;
        }
        __syncthreads();

#pragma unroll
        for (int s = 0; s < 3; s++) {
            int Ab = (s == 1) ? ALO : AHI;
            int Bb = (s == 2) ? BLO : BHI;
#pragma unroll
            for (int ks = 0; ks < 4; ks++) {
                uint32_t ra[2][4];
#pragma unroll
                for (int mt = 0; mt < 2; mt++) {
                    int r = wm * 32 + mt * 16 + gid;
                    const char* p = sm + Ab + r * SMS + (ks * 16 + tig * 2) * 2;
                    ra[mt][0] = *(const uint32_t*)p;
                    ra[mt][1] = *(const uint32_t*)(p + 8 * SMS);
                    ra[mt][2] = *(const uint32_t*)(p + 16);
                    ra[mt][3] = *(const uint32_t*)(p + 8 * SMS + 16);
                }
#pragma unroll
                for (int nt = 0; nt < 8; nt++) {
                    int nr = wn * 64 + nt * 8 + gid;
                    const char* p = sm + Bb + nr * SMS + (ks * 16 + tig * 2) * 2;
                    uint32_t rb[2];
                    rb[0] = *(const uint32_t*)p;
                    rb[1] = *(const uint32_t*)(p + 16);
                    mma_bf16(acc[0][nt], ra[0], rb);
                    mma_bf16(acc[1][nt], ra[1], rb);
                }
            }
        }
        __syncthreads();
    }

#pragma unroll
    for (int mt = 0; mt < 2; mt++) {
        int row0 = r0 + wm * 32 + mt * 16 + gid;
        int row1 = row0 + 8;
        float dv0 = 0.f, dv1 = 0.f;
        if (MODE == 1) {
            dv0 = (row0 < n) ? dinv[row0] : 0.f;
            dv1 = (row1 < n) ? dinv[row1] : 0.f;
        }
#pragma unroll
        for (int nt = 0; nt < 8; nt++) {
            int col = wn * 64 + nt * 8 + tig * 2;
            float d0 = acc[mt][nt][0], d1 = acc[mt][nt][1];
            float d2 = acc[mt][nt][2], d3 = acc[mt][nt][3];
            if (MODE == 1) { d0 *= dv0; d1 *= dv0; d2 *= dv1; d3 *= dv1; }
            if (MODE == 2) {
                float b0 = __ldg(bias + col), b1 = __ldg(bias + col + 1);
                d0 = fmaxf(d0 + b0, 0.f); d1 = fmaxf(d1 + b1, 0.f);
                d2 = fmaxf(d2 + b0, 0.f); d3 = fmaxf(d3 + b1, 0.f);
            }
            if (row0 < n) *(float2*)(C + (size_t)row0 * HD + col) = make_float2(d0, d1);
            if (row1 < n) *(float2*)(C + (size_t)row1 * HD + col) = make_float2(d2, d3);
        }
    }
}

// ================= CSR aggregation (8-way unrolled gather) =================
__global__ void aggregate_k(const float* __restrict__ t2,
                            const float* __restrict__ bias,
                            float* __restrict__ out, int n) {
    int w = (blockIdx.x * blockDim.x + threadIdx.x) >> 5;
    int lane = threadIdx.x & 31;
    if (w >= n) return;
    const float4* T = (const float4*)t2;
    float4 acc = T[(size_t)w * 32 + lane];
    int s0 = g_off[w], cnt = g_deg[w];
    int i = 0;
    for (; i + 7 < cnt; i += 8) {
        int ix[8];
#pragma unroll
        for (int u = 0; u < 8; u++) ix[u] = g_csr[s0 + i + u];
        float4 v[8];
#pragma unroll
        for (int u = 0; u < 8; u++) v[u] = T[(size_t)ix[u] * 32 + lane];
#pragma unroll
        for (int u = 0; u < 8; u++) {
            acc.x += v[u].x; acc.y += v[u].y; acc.z += v[u].z; acc.w += v[u].w;
        }
    }
    for (; i < cnt; i++) {
        float4 v = T[(size_t)g_csr[s0 + i] * 32 + lane];
        acc.x += v.x; acc.y += v.y; acc.z += v.z; acc.w += v.w;
    }
    float dvv = g_dinv[w];
    float4 b4 = ((const float4*)bias)[lane];
    float4 o;
    o.x = acc.x * dvv + b4.x; o.y = acc.y * dvv + b4.y;
    o.z = acc.z * dvv + b4.z; o.w = acc.w * dvv + b4.w;
    ((float4*)out)[(size_t)w * 32 + lane] = o;
}

// ================= launch =================
#define SMEM_GEMM 73728

extern "C" void kernel_launch(void* const* d_in, const int* in_sizes, int n_in,
                              void* d_out, int out_size) {
    const float* z   = (const float*)d_in[0];
    const int*   ei  = (const int*)d_in[1];
    const float* Wih = (const float*)d_in[2];
    const float* bih = (const float*)d_in[4];
    const float* bhh = (const float*)d_in[5];
    const float* W1  = (const float*)d_in[6];
    const float* b1  = (const float*)d_in[7];
    const float* W2  = (const float*)d_in[8];
    const float* b2  = (const float*)d_in[9];
    const float* W3  = (const float*)d_in[10];
    const float* b3  = (const float*)d_in[11];

    int n = in_sizes[0] / HD;
    int e = in_sizes[1] / 2;
    float* out = (float*)d_out;

    float *p_h, *p_t, *p_s, *p_dinv;
    __nv_bfloat16* p_wb;
    cudaGetSymbolAddress((void**)&p_h, g_h);
    cudaGetSymbolAddress((void**)&p_t, g_t);
    cudaGetSymbolAddress((void**)&p_s, g_s);
    cudaGetSymbolAddress((void**)&p_dinv, g_dinv);
    cudaGetSymbolAddress((void**)&p_wb, g_wb);

    cudaFuncSetAttribute(lstm_fused, cudaFuncAttributeMaxDynamicSharedMemorySize, L_TOT);
    cudaFuncSetAttribute(mma_gemm<1, false>, cudaFuncAttributeMaxDynamicSharedMemorySize, SMEM_GEMM);
    cudaFuncSetAttribute(mma_gemm<1, true>,  cudaFuncAttributeMaxDynamicSharedMemorySize, SMEM_GEMM);
    cudaFuncSetAttribute(mma_gemm<2, false>, cudaFuncAttributeMaxDynamicSharedMemorySize, SMEM_GEMM);

    int nb = (n + 1023) / 1024;
    // order chosen so the 4th launch (ncu's capture point) is lstm_fused
    prep_weights<<<(HD * HD + 255) / 256, 256>>>(Wih, W1, W2, W3, bih, bhh);   // 1
    zero_deg<<<(n + 255) / 256, 256>>>(n);                                     // 2
    deg_count<<<(e + 255) / 256, 256>>>(ei, e);                                // 3
    lstm_fused<<<(n + 63) / 64, 256, L_TOT>>>(z, n);                           // 4 <- profiled
    scan1<<<nb, 1024>>>(n);
    scan2<<<1, 128>>>(nb);
    scan3<<<(n + 255) / 256, 256>>>(n);
    csr_fill<<<(e + 255) / 256, 256>>>(ei, e);

    dim3 gg((n + 127) / 128);
    // conv1 transform: t = (h @ W1) * dinv[row]
    mma_gemm<1, false><<<gg, 256, SMEM_GEMM>>>(p_h, p_wb + 3 * 32768, nullptr, p_dinv, p_t, n);
    aggregate_k<<<((size_t)n * 32 + 255) / 256, 256>>>(p_t, b1, p_s, n);
    // conv2 transform: t = (relu(s) @ W2) * dinv[row]
    mma_gemm<1, true><<<gg, 256, SMEM_GEMM>>>(p_s, p_wb + 4 * 32768, nullptr, p_dinv, p_t, n);
    aggregate_k<<<((size_t)n * 32 + 255) / 256, 256>>>(p_t, b2, p_s, n);
    // final: out = relu(s @ W3^T + b3)
    mma_gemm<2, false><<<gg, 256, SMEM_GEMM>>>(p_s, p_wb + 5 * 32768, b3, nullptr, out, n);
}

// round 6
// speedup vs baseline: 1.5547x; 1.0700x over previous
#include <cuda_runtime.h>
#include <cuda_bf16.h>
#include <math.h>
#include <stdint.h>

#define HD 128
#define NMAX 100000
#define EMAX 1600000

// ================= scratch (static device memory) =================
__device__ float g_h[(size_t)NMAX * HD];
__device__ float g_t[(size_t)NMAX * HD];
__device__ float g_s[(size_t)NMAX * HD];
__device__ float g_dinv[NMAX];
__device__ int   g_deg[NMAX];
__device__ int   g_off[NMAX];
__device__ int   g_cur[NMAX];
__device__ int   g_csr[EMAX];
__device__ int   g_bsums[256];
__device__ float g_gb[3 * HD];                       // combined gate biases (i,g,o)
__device__ __align__(16) __nv_bfloat16 g_wb[6 * 2 * HD * HD];  // [plane][hi/lo][128*128]
// planes: 0,1,2 = W_ih gate blocks (i,g,o) as [n][k]; 3 = W1^T; 4 = W2^T; 5 = W3

__device__ __forceinline__ void split_bf16(float v, __nv_bfloat16& h, __nv_bfloat16& l) {
    h = __float2bfloat16(v);
    l = __float2bfloat16(v - __bfloat162float(h));
}

// ================= prep =================
__global__ void prep_weights(const float* __restrict__ Wih,
                             const float* __restrict__ W1,
                             const float* __restrict__ W2,
                             const float* __restrict__ W3,
                             const float* __restrict__ bih,
                             const float* __restrict__ bhh) {
    int idx = blockIdx.x * blockDim.x + threadIdx.x;
    if (idx >= HD * HD) return;
    int nn = idx >> 7, kk = idx & 127;
    const int G[3] = {0, 256, 384};
    float src[6];
    src[0] = Wih[(G[0] + nn) * HD + kk];
    src[1] = Wih[(G[1] + nn) * HD + kk];
    src[2] = Wih[(G[2] + nn) * HD + kk];
    src[3] = W1[kk * HD + nn];
    src[4] = W2[kk * HD + nn];
    src[5] = W3[nn * HD + kk];
#pragma unroll
    for (int p = 0; p < 6; p++) {
        __nv_bfloat16 h, l;
        split_bf16(src[p], h, l);
        g_wb[p * 32768 + idx] = h;
        g_wb[p * 32768 + 16384 + idx] = l;
    }
    if (idx < 3 * HD) {
        int p = idx / HD, j = idx % HD;
        g_gb[idx] = bih[G[p] + j] + bhh[G[p] + j];
    }
}

// ================= degree / scan / CSR =================
__global__ void zero_deg(int n) {
    int i = blockIdx.x * blockDim.x + threadIdx.x;
    if (i < n) g_deg[i] = 0;
}
__global__ void deg_count(const int* __restrict__ ei, int e) {
    int i = blockIdx.x * blockDim.x + threadIdx.x;
    if (i < e) atomicAdd(&g_deg[ei[e + i]], 1);
}
__global__ void scan1(int n) {
    __shared__ int sm[1024];
    int t = threadIdx.x, i = blockIdx.x * 1024 + t;
    int v = (i < n) ? g_deg[i] : 0;
    if (i < n) g_dinv[i] = rsqrtf((float)v + 1.0f);   // fused dinv
    sm[t] = v; __syncthreads();
    for (int o = 1; o < 1024; o <<= 1) {
        int tmp = (t >= o) ? sm[t - o] : 0; __syncthreads();
        sm[t] += tmp; __syncthreads();
    }
    if (i < n) g_off[i] = sm[t] - v;
    if (t == 1023) g_bsums[blockIdx.x] = sm[1023];
}
__global__ void scan2(int nb) {
    __shared__ int sm[128];
    int t = threadIdx.x;
    int v = (t < nb) ? g_bsums[t] : 0;
    sm[t] = v; __syncthreads();
    for (int o = 1; o < 128; o <<= 1) {
        int tmp = (t >= o) ? sm[t - o] : 0; __syncthreads();
        sm[t] += tmp; __syncthreads();
    }
    if (t < nb) g_bsums[t] = sm[t] - v;
}
__global__ void scan3(int n) {
    int i = blockIdx.x * blockDim.x + threadIdx.x;
    if (i < n) {
        int o = g_off[i] + g_bsums[i >> 10];
        g_off[i] = o; g_cur[i] = o;
    }
}
__global__ void csr_fill(const int* __restrict__ ei, int e) {
    int i = blockIdx.x * blockDim.x + threadIdx.x;
    if (i < e) {
        int d = ei[e + i];
        g_csr[atomicAdd(&g_cur[d], 1)] = ei[i];
    }
}

// ================= mma helpers =================
__device__ __forceinline__ void mma_bf16(float* d, const uint32_t* a, const uint32_t* b) {
    asm volatile(
        "mma.sync.aligned.m16n8k16.row.col.f32.bf16.bf16.f32 "
        "{%0,%1,%2,%3}, {%4,%5,%6,%7}, {%8,%9}, {%0,%1,%2,%3};"
        : "+f"(d[0]), "+f"(d[1]), "+f"(d[2]), "+f"(d[3])
        : "r"(a[0]), "r"(a[1]), "r"(a[2]), "r"(a[3]), "r"(b[0]), "r"(b[1]));
}

// ================= fused LSTM: h = act(z @ {Wi,Wg,Wo}^T + gb) =================
// 64-row tile, K=128 A resident; B loaded per-plane in two 64-k chunks so
// smem stays under half-SM -> 2 CTAs/SM.
#define SMS2 272          // A row stride bytes
#define BSTR 144          // B chunk row stride bytes
#define L_AHI 0
#define L_ALO 17408
#define L_BHI 34816       // 128 x 144
#define L_BLO 53248
#define L_TOT 71680

__global__ void __launch_bounds__(256, 2)
lstm_fused(const float* __restrict__ z, int n) {
    extern __shared__ char sm[];
    int tid = threadIdx.x, lane = tid & 31, wid = tid >> 5;
    int gid = lane >> 2, tig = lane & 3;
    int wm = wid >> 2, wn = wid & 3;            // 2 m x 4 n warps
    int r0 = blockIdx.x * 64;

    // ---- load + split A (64 x 128) ----
    for (int i = tid; i < 64 * 32; i += 256) {
        int row = i >> 5, q = i & 31;
        float4 v = make_float4(0.f, 0.f, 0.f, 0.f);
        if (r0 + row < n) v = *(const float4*)(z + (size_t)(r0 + row) * HD + q * 4);
        __nv_bfloat16 h[4], l[4];
        split_bf16(v.x, h[0], l[0]); split_bf16(v.y, h[1], l[1]);
        split_bf16(v.z, h[2], l[2]); split_bf16(v.w, h[3], l[3]);
        *(uint2*)(sm + L_AHI + row * SMS2 + q * 8) = *(const uint2*)h;
        *(uint2*)(sm + L_ALO + row * SMS2 + q * 8) = *(const uint2*)l;
    }

    float cp[2][4][4];   // running c (then h)
    float acc[2][4][4];

#pragma unroll 1
    for (int p = 0; p < 3; p++) {
#pragma unroll
        for (int mt = 0; mt < 2; mt++)
#pragma unroll
            for (int nt = 0; nt < 4; nt++)
#pragma unroll
                for (int q = 0; q < 4; q++) acc[mt][nt][q] = 0.0f;

#pragma unroll 1
        for (int kc = 0; kc < 2; kc++) {
            __syncthreads();   // prior MMA frag reads done before B overwrite
            // ---- load B plane p, k-chunk kc (128 n x 64 k, hi/lo) ----
            for (int i = tid; i < 128 * 8; i += 256) {
                int row = i >> 3, q = i & 7;
                uint4 h = *(const uint4*)(g_wb + (size_t)p * 32768 + row * HD + kc * 64 + q * 8);
                uint4 l = *(const uint4*)(g_wb + (size_t)p * 32768 + 16384 + row * HD + kc * 64 + q * 8);
                *(uint4*)(sm + L_BHI + row * BSTR + q * 16) = h;
                *(uint4*)(sm + L_BLO + row * BSTR + q * 16) = l;
            }
            __syncthreads();

#pragma unroll
            for (int s = 0; s < 3; s++) {
                int Ab = (s == 1) ? L_ALO : L_AHI;
                int Bb = (s == 2) ? L_BLO : L_BHI;
#pragma unroll
                for (int ks = 0; ks < 4; ks++) {
                    uint32_t ra[2][4];
#pragma unroll
                    for (int mt = 0; mt < 2; mt++) {
                        int r = wm * 32 + mt * 16 + gid;
                        const char* pp = sm + Ab + r * SMS2 + (kc * 64 + ks * 16 + tig * 2) * 2;
                        ra[mt][0] = *(const uint32_t*)pp;
                        ra[mt][1] = *(const uint32_t*)(pp + 8 * SMS2);
                        ra[mt][2] = *(const uint32_t*)(pp + 16);
                        ra[mt][3] = *(const uint32_t*)(pp + 8 * SMS2 + 16);
                    }
#pragma unroll
                    for (int nt = 0; nt < 4; nt++) {
                        int nr = wn * 32 + nt * 8 + gid;
                        const char* pp = sm + Bb + nr * BSTR + (ks * 16 + tig * 2) * 2;
                        uint32_t rb[2];
                        rb[0] = *(const uint32_t*)pp;
                        rb[1] = *(const uint32_t*)(pp + 16);
                        mma_bf16(acc[0][nt], ra[0], rb);
                        mma_bf16(acc[1][nt], ra[1], rb);
                    }
                }
            }
        }

        // ---- plane epilogue (registers only) ----
#pragma unroll
        for (int mt = 0; mt < 2; mt++) {
#pragma unroll
            for (int nt = 0; nt < 4; nt++) {
                int col = wn * 32 + nt * 8 + tig * 2;
                float2 bg = *(const float2*)(g_gb + p * HD + col);
#pragma unroll
                for (int q = 0; q < 4; q++) {
                    float gv = acc[mt][nt][q] + ((q & 1) ? bg.y : bg.x);
                    if (p == 0)      cp[mt][nt][q] = 1.0f / (1.0f + __expf(-gv));
                    else if (p == 1) cp[mt][nt][q] = cp[mt][nt][q] * tanhf(gv);
                    else             cp[mt][nt][q] = (1.0f / (1.0f + __expf(-gv))) * tanhf(cp[mt][nt][q]);
                }
            }
        }
    }

    // ---- store h ----
#pragma unroll
    for (int mt = 0; mt < 2; mt++) {
        int row0 = r0 + wm * 32 + mt * 16 + gid;
        int row1 = row0 + 8;
#pragma unroll
        for (int nt = 0; nt < 4; nt++) {
            int col = wn * 32 + nt * 8 + tig * 2;
            if (row0 < n) *(float2*)(g_h + (size_t)row0 * HD + col) = make_float2(cp[mt][nt][0], cp[mt][nt][1]);
            if (row1 < n) *(float2*)(g_h + (size_t)row1 * HD + col) = make_float2(cp[mt][nt][2], cp[mt][nt][3]);
        }
    }
}

// ================= mma.sync split GEMM (single plane) =================
#define SMS 144
template <int MODE, bool ARELU>
__global__ void __launch_bounds__(256, 2)
mma_gemm(const float* __restrict__ A, const __nv_bfloat16* __restrict__ Bp,
         const float* __restrict__ bias, const float* __restrict__ dinv,
         float* __restrict__ C, int n) {
    extern __shared__ char sm[];
    const int AHI = 0, ALO = 18432, BHI = 36864, BLO = 55296;

    int tid = threadIdx.x, lane = tid & 31, wid = tid >> 5;
    int gid = lane >> 2, tig = lane & 3;
    int wm = wid & 3, wn = wid >> 2;
    int r0 = blockIdx.x * 128;

    float acc[2][8][4];
#pragma unroll
    for (int mt = 0; mt < 2; mt++)
#pragma unroll
        for (int nt = 0; nt < 8; nt++)
#pragma unroll
            for (int q = 0; q < 4; q++) acc[mt][nt][q] = 0.0f;

#pragma unroll 1
    for (int kc = 0; kc < 2; kc++) {
        for (int i = tid; i < 128 * 16; i += 256) {
            int row = i >> 4, q = i & 15;
            float4 v = make_float4(0.f, 0.f, 0.f, 0.f);
            if (r0 + row < n)
                v = *(const float4*)(A + (size_t)(r0 + row) * HD + kc * 64 + q * 4);
            if (ARELU) {
                v.x = fmaxf(v.x, 0.f); v.y = fmaxf(v.y, 0.f);
                v.z = fmaxf(v.z, 0.f); v.w = fmaxf(v.w, 0.f);
            }
            __nv_bfloat16 h[4], l[4];
            split_bf16(v.x, h[0], l[0]); split_bf16(v.y, h[1], l[1]);
            split_bf16(v.z, h[2], l[2]); split_bf16(v.w, h[3], l[3]);
            *(uint2*)(sm + AHI + row * SMS + q * 8) = *(const uint2*)h;
            *(uint2*)(sm + ALO + row * SMS + q * 8) = *(const uint2*)l;
        }
        for (int i = tid; i < 128 * 8; i += 256) {
            int row = i >> 3, q = i & 7;
            uint4 h = *(const uint4*)(Bp + (size_t)row * HD + kc * 64 + q * 8);
            uint4 l = *(const uint4*)(Bp + 16384 + (size_t)row * HD + kc * 64 + q * 8);
            *(uint4*)(sm + BHI + row * SMS + q * 16) = h;
            *(uint4*)(sm + BLO + row * SMS + q * 16) = l;
        }
        __syncthreads();

#pragma unroll
        for (int s = 0; s < 3; s++) {
            int Ab = (s == 1) ? ALO : AHI;
            int Bb = (s == 2) ? BLO : BHI;
#pragma unroll
            for (int ks = 0; ks < 4; ks++) {
                uint32_t ra[2][4];
#pragma unroll
                for (int mt = 0; mt < 2; mt++) {
                    int r = wm * 32 + mt * 16 + gid;
                    const char* p = sm + Ab + r * SMS + (ks * 16 + tig * 2) * 2;
                    ra[mt][0] = *(const uint32_t*)p;
                    ra[mt][1] = *(const uint32_t*)(p + 8 * SMS);
                    ra[mt][2] = *(const uint32_t*)(p + 16);
                    ra[mt][3] = *(const uint32_t*)(p + 8 * SMS + 16);
                }
#pragma unroll
                for (int nt = 0; nt < 8; nt++) {
                    int nr = wn * 64 + nt * 8 + gid;
                    const char* p = sm + Bb + nr * SMS + (ks * 16 + tig * 2) * 2;
                    uint32_t rb[2];
                    rb[0] = *(const uint32_t*)p;
                    rb[1] = *(const uint32_t*)(p + 16);
                    mma_bf16(acc[0][nt], ra[0], rb);
                    mma_bf16(acc[1][nt], ra[1], rb);
                }
            }
        }
        __syncthreads();
    }

#pragma unroll
    for (int mt = 0; mt < 2; mt++) {
        int row0 = r0 + wm * 32 + mt * 16 + gid;
        int row1 = row0 + 8;
        float dv0 = 0.f, dv1 = 0.f;
        if (MODE == 1) {
            dv0 = (row0 < n) ? dinv[row0] : 0.f;
            dv1 = (row1 < n) ? dinv[row1] : 0.f;
        }
#pragma unroll
        for (int nt = 0; nt < 8; nt++) {
            int col = wn * 64 + nt * 8 + tig * 2;
            float d0 = acc[mt][nt][0], d1 = acc[mt][nt][1];
            float d2 = acc[mt][nt][2], d3 = acc[mt][nt][3];
            if (MODE == 1) { d0 *= dv0; d1 *= dv0; d2 *= dv1; d3 *= dv1; }
            if (MODE == 2) {
                float b0 = __ldg(bias + col), b1 = __ldg(bias + col + 1);
                d0 = fmaxf(d0 + b0, 0.f); d1 = fmaxf(d1 + b1, 0.f);
                d2 = fmaxf(d2 + b0, 0.f); d3 = fmaxf(d3 + b1, 0.f);
            }
            if (row0 < n) *(float2*)(C + (size_t)row0 * HD + col) = make_float2(d0, d1);
            if (row1 < n) *(float2*)(C + (size_t)row1 * HD + col) = make_float2(d2, d3);
        }
    }
}

// ================= CSR aggregation (8-way unrolled gather) =================
__global__ void aggregate_k(const float* __restrict__ t2,
                            const float* __restrict__ bias,
                            float* __restrict__ out, int n) {
    int w = (blockIdx.x * blockDim.x + threadIdx.x) >> 5;
    int lane = threadIdx.x & 31;
    if (w >= n) return;
    const float4* T = (const float4*)t2;
    float4 acc = T[(size_t)w * 32 + lane];
    int s0 = g_off[w], cnt = g_deg[w];
    int i = 0;
    for (; i + 7 < cnt; i += 8) {
        int ix[8];
#pragma unroll
        for (int u = 0; u < 8; u++) ix[u] = g_csr[s0 + i + u];
        float4 v[8];
#pragma unroll
        for (int u = 0; u < 8; u++) v[u] = T[(size_t)ix[u] * 32 + lane];
#pragma unroll
        for (int u = 0; u < 8; u++) {
            acc.x += v[u].x; acc.y += v[u].y; acc.z += v[u].z; acc.w += v[u].w;
        }
    }
    for (; i < cnt; i++) {
        float4 v = T[(size_t)g_csr[s0 + i] * 32 + lane];
        acc.x += v.x; acc.y += v.y; acc.z += v.z; acc.w += v.w;
    }
    float dvv = g_dinv[w];
    float4 b4 = ((const float4*)bias)[lane];
    float4 o;
    o.x = acc.x * dvv + b4.x; o.y = acc.y * dvv + b4.y;
    o.z = acc.z * dvv + b4.z; o.w = acc.w * dvv + b4.w;
    ((float4*)out)[(size_t)w * 32 + lane] = o;
}

// ================= launch =================
#define SMEM_GEMM 73728

extern "C" void kernel_launch(void* const* d_in, const int* in_sizes, int n_in,
                              void* d_out, int out_size) {
    const float* z   = (const float*)d_in[0];
    const int*   ei  = (const int*)d_in[1];
    const float* Wih = (const float*)d_in[2];
    const float* bih = (const float*)d_in[4];
    const float* bhh = (const float*)d_in[5];
    const float* W1  = (const float*)d_in[6];
    const float* b1  = (const float*)d_in[7];
    const float* W2  = (const float*)d_in[8];
    const float* b2  = (const float*)d_in[9];
    const float* W3  = (const float*)d_in[10];
    const float* b3  = (const float*)d_in[11];

    int n = in_sizes[0] / HD;
    int e = in_sizes[1] / 2;
    float* out = (float*)d_out;

    float *p_h, *p_t, *p_s, *p_dinv;
    __nv_bfloat16* p_wb;
    cudaGetSymbolAddress((void**)&p_h, g_h);
    cudaGetSymbolAddress((void**)&p_t, g_t);
    cudaGetSymbolAddress((void**)&p_s, g_s);
    cudaGetSymbolAddress((void**)&p_dinv, g_dinv);
    cudaGetSymbolAddress((void**)&p_wb, g_wb);

    cudaFuncSetAttribute(lstm_fused, cudaFuncAttributeMaxDynamicSharedMemorySize, L_TOT);
    cudaFuncSetAttribute(mma_gemm<1, false>, cudaFuncAttributeMaxDynamicSharedMemorySize, SMEM_GEMM);
    cudaFuncSetAttribute(mma_gemm<1, true>,  cudaFuncAttributeMaxDynamicSharedMemorySize, SMEM_GEMM);
    cudaFuncSetAttribute(mma_gemm<2, false>, cudaFuncAttributeMaxDynamicSharedMemorySize, SMEM_GEMM);

    int nb = (n + 1023) / 1024;
    // same kernel ordering as R5 so ncu's capture slot again lands on lstm_fused
    prep_weights<<<(HD * HD + 255) / 256, 256>>>(Wih, W1, W2, W3, bih, bhh);   // 1
    zero_deg<<<(n + 255) / 256, 256>>>(n);                                     // 2
    deg_count<<<(e + 255) / 256, 256>>>(ei, e);                                // 3
    lstm_fused<<<(n + 63) / 64, 256, L_TOT>>>(z, n);                           // 4 <- profiled
    scan1<<<nb, 1024>>>(n);
    scan2<<<1, 128>>>(nb);
    scan3<<<(n + 255) / 256, 256>>>(n);
    csr_fill<<<(e + 255) / 256, 256>>>(ei, e);

    dim3 gg((n + 127) / 128);
    mma_gemm<1, false><<<gg, 256, SMEM_GEMM>>>(p_h, p_wb + 3 * 32768, nullptr, p_dinv, p_t, n);
    aggregate_k<<<((size_t)n * 32 + 255) / 256, 256>>>(p_t, b1, p_s, n);
    mma_gemm<1, true><<<gg, 256, SMEM_GEMM>>>(p_s, p_wb + 4 * 32768, nullptr, p_dinv, p_t, n);
    aggregate_k<<<((size_t)n * 32 + 255) / 256, 256>>>(p_t, b2, p_s, n);
    mma_gemm<2, false><<<gg, 256, SMEM_GEMM>>>(p_s, p_wb + 5 * 32768, b3, nullptr, out, n);
}